// round 7
// baseline (speedup 1.0000x reference)
#include <cuda_runtime.h>

#define S 1024
#define G 10
#define F 5
#define B 8
#define C 3
#define KW (2*F+1)

// ---------------------------------------------------------------------------
// Single fused kernel: one block per (row y, batch b).
// Prologue (few warps): separable 11x11 edge-clamped conv of the 10x10 offset
// fields, clip, y-interpolate to this row's 10-wide (gx,gy) field.
// Main loop: 256 threads x 4 pixels, bilinear grid_sample, float4 stores.
// ---------------------------------------------------------------------------
__global__ __launch_bounds__(256, 4) void deform_fused_kernel(
        const float* __restrict__ xin,
        const float* __restrict__ ox,
        const float* __restrict__ oy,
        const float* __restrict__ w,
        const void* __restrict__ mm_p,
        float* __restrict__ out) {
    __shared__ float  sh[2][G][G];     // horizontal conv pass
    __shared__ float  sg[2][2][G];     // vertical pass at rows i0, i1
    __shared__ float2 srow[G];         // final per-row coarse field

    const int b   = blockIdx.y;
    const int y   = blockIdx.x;
    const int tid = threadIdx.x;

    // Row interpolation parameters (all threads compute; cheap)
    float srcy = fmaxf((y + 0.5f) * ((float)G / (float)S) - 0.5f, 0.0f);
    int i0 = min((int)srcy, G - 1);
    int i1 = min(i0 + 1, G - 1);
    float wr = srcy - (float)i0;

    // --- Phase 1: horizontal conv pass: h[ch][i][j] = sum_v w[F][v]*o[i][clamp(j+v-F)]
    if (tid < 2 * G * G) {
        int ch  = tid / (G * G);
        int rem = tid % (G * G);
        int i   = rem / G;
        int j   = rem % G;
        const float* o = (ch ? oy : ox) + b * G * G + i * G;
        float acc = 0.0f;
        #pragma unroll
        for (int v = 0; v < KW; v++) {
            int jj = min(max(j + v - F, 0), G - 1);
            acc = fmaf(w[F * KW + v], o[jj], acc);
        }
        sh[ch][i][j] = acc;
    }
    __syncthreads();

    // --- Phase 2: vertical pass at rows i0/i1, scale + clip
    if (tid < 2 * 2 * G) {
        int j   = tid % G;
        int sel = (tid / G) & 1;
        int ch  = tid / (2 * G);
        int row = sel ? i1 : i0;

        // max_move may arrive as int32 or float32 — decode robustly.
        int raw = *(const int*)mm_p;
        float mmv = (raw >= 0 && raw < 1000000) ? (float)raw : __int_as_float(raw);
        float max_offset = 2.0f * mmv / (float)S;

        float wff = w[F * KW + F];
        float acc = 0.0f;
        #pragma unroll
        for (int u = 0; u < KW; u++) {
            int ii = min(max(row + u - F, 0), G - 1);
            acc = fmaf(w[u * KW + F], sh[ch][ii][j], acc);
        }
        acc *= max_offset / wff;   // separable: w[u][v] = w[u][F]*w[F][v]/w[F][F]
        acc = fminf(fmaxf(acc, -max_offset), max_offset);
        sg[ch][sel][j] = acc;
    }
    __syncthreads();

    // --- Phase 3: y-interpolate into the row field
    if (tid < G) {
        float gx = sg[0][0][tid] * (1.0f - wr) + sg[0][1][tid] * wr;
        float gy = sg[1][0][tid] * (1.0f - wr) + sg[1][1][tid] * wr;
        srow[tid] = make_float2(gx, gy);
    }
    __syncthreads();

    // --- Main loop: 4 pixels per thread
    const int xbase = tid * 4;
    const float* xb = xin + (size_t)b * C * S * S;
    const float Py  = fmaf((float)y, 2.0f / (float)(S - 1), -1.0f);

    float4 acc0, acc1, acc2;
    float* a0 = (float*)&acc0;
    float* a1 = (float*)&acc1;
    float* a2 = (float*)&acc2;

    #pragma unroll
    for (int p = 0; p < 4; p++) {
        const int x = xbase + p;

        float srcx = fmaxf((x + 0.5f) * ((float)G / (float)S) - 0.5f, 0.0f);
        int j0 = min((int)srcx, G - 1);
        int j1 = min(j0 + 1, G - 1);
        float wc = srcx - (float)j0;
        float2 fa = srow[j0];
        float2 fb = srow[j1];
        float gx = fa.x * (1.0f - wc) + fb.x * wc;
        float gy = fa.y * (1.0f - wc) + fb.y * wc;

        float Px = fmaf((float)x, 2.0f / (float)(S - 1), -1.0f);
        float g0 = fminf(fmaxf(gx + Px, -1.0f), 1.0f);
        float g1 = fminf(fmaxf(gy + Py, -1.0f), 1.0f);

        // ((g+1)*S - 1) / 2 == g*512 + 511.5
        float ix = fmaf(g0, 512.0f, 511.5f);
        float iy = fmaf(g1, 512.0f, 511.5f);

        float fx = floorf(ix);
        float fy = floorf(iy);
        int x0 = (int)fx;
        int y0 = (int)fy;
        float wx = ix - fx;
        float wy = iy - fy;
        int x1 = x0 + 1;
        int y1 = y0 + 1;

        // ix in [-0.5, 1023.5]: only low side of x0 / high side of x1 can be OOB
        float wxa = (x0 >= 0)     ? (1.0f - wx) : 0.0f;
        float wxb = (x1 <= S - 1) ? wx          : 0.0f;
        float wya = (y0 >= 0)     ? (1.0f - wy) : 0.0f;
        float wyb = (y1 <= S - 1) ? wy          : 0.0f;

        int cx0 = max(x0, 0);
        int cx1 = min(x1, S - 1);
        int cy0 = max(y0, 0);
        int cy1 = min(y1, S - 1);

        float w00 = wya * wxa;
        float w01 = wya * wxb;
        float w10 = wyb * wxa;
        float w11 = wyb * wxb;

        int o00 = cy0 * S + cx0;
        int o01 = cy0 * S + cx1;
        int o10 = cy1 * S + cx0;
        int o11 = cy1 * S + cx1;

        {
            const float* img = xb;
            a0[p] = img[o00] * w00 + img[o01] * w01 + img[o10] * w10 + img[o11] * w11;
        }
        {
            const float* img = xb + S * S;
            a1[p] = img[o00] * w00 + img[o01] * w01 + img[o10] * w10 + img[o11] * w11;
        }
        {
            const float* img = xb + 2 * S * S;
            a2[p] = img[o00] * w00 + img[o01] * w01 + img[o10] * w10 + img[o11] * w11;
        }
    }

    float* ob = out + (((size_t)(b * C) * S) + y) * S + xbase;
    *(float4*)(ob)             = acc0;
    *(float4*)(ob + S * S)     = acc1;
    *(float4*)(ob + 2 * S * S) = acc2;
}

extern "C" void kernel_launch(void* const* d_in, const int* in_sizes, int n_in,
                              void* d_out, int out_size) {
    const float* x  = (const float*)d_in[0];
    const float* ox = (const float*)d_in[1];
    const float* oy = (const float*)d_in[2];
    const float* w  = (const float*)d_in[3];
    const void*  mm = d_in[4];

    dim3 grid(S, B);
    deform_fused_kernel<<<grid, 256>>>(x, ox, oy, w, mm, (float*)d_out);
}

// round 8
// speedup vs baseline: 1.1925x; 1.1925x over previous
#include <cuda_runtime.h>

#define S 1024
#define G 10
#define F 5
#define B 8
#define C 3
#define KW (2*F+1)
#define RPB 4                 // rows per block
#define NXB (S / 256)         // x-positions per thread (4)

// ---------------------------------------------------------------------------
// Fused kernel: one block per (4 rows, batch). Prologue: separable 11x11
// edge-clamped conv (outer-product Gaussian) + y-interp for the 4 rows.
// Main loop: strided pixel mapping (x = tid + 256*p) so all gathers and
// stores are warp-coalesced.
// ---------------------------------------------------------------------------
__global__ __launch_bounds__(256, 4) void deform_fused_kernel(
        const float* __restrict__ xin,
        const float* __restrict__ ox,
        const float* __restrict__ oy,
        const float* __restrict__ w,
        const void* __restrict__ mm_p,
        float* __restrict__ out) {
    __shared__ float  sh[2][G][G];        // horizontal conv pass
    __shared__ float  sg[RPB][2][2][G];   // vertical pass at rows i0,i1 per row
    __shared__ float2 srow[RPB][G];       // final per-row coarse fields

    const int b     = blockIdx.y;
    const int ybase = blockIdx.x * RPB;
    const int tid   = threadIdx.x;

    // --- Phase 1: horizontal pass  h[ch][i][j] = sum_v w[F][v] * o[i][clamp(j+v-F)]
    if (tid < 2 * G * G) {
        int ch  = tid / (G * G);
        int rem = tid % (G * G);
        int i   = rem / G;
        int j   = rem % G;
        const float* o = (ch ? oy : ox) + b * G * G + i * G;
        float acc = 0.0f;
        #pragma unroll
        for (int v = 0; v < KW; v++) {
            int jj = min(max(j + v - F, 0), G - 1);
            acc = fmaf(__ldg(&w[F * KW + v]), __ldg(&o[jj]), acc);
        }
        sh[ch][i][j] = acc;
    }
    __syncthreads();

    // --- Phase 2: vertical pass at rows i0/i1 for each of the RPB rows
    if (tid < RPB * 2 * 2 * G) {
        int j   = tid % G;
        int sel = (tid / G) & 1;
        int ch  = (tid / (2 * G)) & 1;
        int r   = tid / (4 * G);
        int y   = ybase + r;

        float srcy = fmaxf((y + 0.5f) * ((float)G / (float)S) - 0.5f, 0.0f);
        int i0 = min((int)srcy, G - 1);
        int row = sel ? min(i0 + 1, G - 1) : i0;

        // max_move may arrive as int32 or float32 — decode robustly.
        int raw = *(const int*)mm_p;
        float mmv = (raw >= 0 && raw < 1000000) ? (float)raw : __int_as_float(raw);
        float max_offset = 2.0f * mmv / (float)S;

        float wff = __ldg(&w[F * KW + F]);
        float acc = 0.0f;
        #pragma unroll
        for (int u = 0; u < KW; u++) {
            int ii = min(max(row + u - F, 0), G - 1);
            acc = fmaf(__ldg(&w[u * KW + F]), sh[ch][ii][j], acc);
        }
        acc *= max_offset / wff;  // separable: w[u][v] = w[u][F]*w[F][v]/w[F][F]
        acc = fminf(fmaxf(acc, -max_offset), max_offset);
        sg[r][ch][sel][j] = acc;
    }
    __syncthreads();

    // --- Phase 3: y-interpolate each row's field
    if (tid < RPB * G) {
        int r = tid / G;
        int j = tid % G;
        int y = ybase + r;
        float srcy = fmaxf((y + 0.5f) * ((float)G / (float)S) - 0.5f, 0.0f);
        int i0 = min((int)srcy, G - 1);
        float wr = srcy - (float)i0;
        float gx = sg[r][0][0][j] * (1.0f - wr) + sg[r][0][1][j] * wr;
        float gy = sg[r][1][0][j] * (1.0f - wr) + sg[r][1][1][j] * wr;
        srow[r][j] = make_float2(gx, gy);
    }
    __syncthreads();

    // --- Main loop: strided pixels, coalesced gathers + stores
    const float* xb = xin + (size_t)b * C * S * S;
    float* obase    = out + (size_t)b * C * S * S;

    float Py[RPB];
    #pragma unroll
    for (int r = 0; r < RPB; r++)
        Py[r] = fmaf((float)(ybase + r), 2.0f / (float)(S - 1), -1.0f);

    #pragma unroll
    for (int p = 0; p < NXB; p++) {
        const int x = tid + p * 256;

        // x-dependent field interp — shared across the RPB rows
        float srcx = fmaxf((x + 0.5f) * ((float)G / (float)S) - 0.5f, 0.0f);
        int j0 = min((int)srcx, G - 1);
        int j1 = min(j0 + 1, G - 1);
        float wc  = srcx - (float)j0;
        float Px  = fmaf((float)x, 2.0f / (float)(S - 1), -1.0f);

        #pragma unroll
        for (int r = 0; r < RPB; r++) {
            float2 fa = srow[r][j0];
            float2 fb = srow[r][j1];
            float gx = fa.x * (1.0f - wc) + fb.x * wc;
            float gy = fa.y * (1.0f - wc) + fb.y * wc;

            float g0 = fminf(fmaxf(gx + Px, -1.0f), 1.0f);
            float g1 = fminf(fmaxf(gy + Py[r], -1.0f), 1.0f);

            // ((g+1)*S - 1) / 2 == g*512 + 511.5
            float ix = fmaf(g0, 512.0f, 511.5f);
            float iy = fmaf(g1, 512.0f, 511.5f);

            float fx = floorf(ix);
            float fy = floorf(iy);
            int x0 = (int)fx;
            int y0 = (int)fy;
            float wx = ix - fx;
            float wy = iy - fy;
            int x1 = x0 + 1;
            int y1 = y0 + 1;

            // ix in [-0.5, 1023.5]: only low of x0 / high of x1 can be OOB
            float wxa = (x0 >= 0)     ? (1.0f - wx) : 0.0f;
            float wxb = (x1 <= S - 1) ? wx          : 0.0f;
            float wya = (y0 >= 0)     ? (1.0f - wy) : 0.0f;
            float wyb = (y1 <= S - 1) ? wy          : 0.0f;

            int cx0 = max(x0, 0);
            int cx1 = min(x1, S - 1);
            int cy0 = max(y0, 0);
            int cy1 = min(y1, S - 1);

            float w00 = wya * wxa;
            float w01 = wya * wxb;
            float w10 = wyb * wxa;
            float w11 = wyb * wxb;

            int o00 = cy0 * S + cx0;
            int o01 = cy0 * S + cx1;
            int o10 = cy1 * S + cx0;
            int o11 = cy1 * S + cx1;

            size_t orow = (size_t)(ybase + r) * S + x;

            #pragma unroll
            for (int c = 0; c < C; c++) {
                const float* img = xb + (size_t)c * S * S;
                float v = img[o00] * w00 + img[o01] * w01
                        + img[o10] * w10 + img[o11] * w11;
                obase[(size_t)c * S * S + orow] = v;
            }
        }
    }
}

extern "C" void kernel_launch(void* const* d_in, const int* in_sizes, int n_in,
                              void* d_out, int out_size) {
    const float* x  = (const float*)d_in[0];
    const float* ox = (const float*)d_in[1];
    const float* oy = (const float*)d_in[2];
    const float* w  = (const float*)d_in[3];
    const void*  mm = d_in[4];

    dim3 grid(S / RPB, B);
    deform_fused_kernel<<<grid, 256>>>(x, ox, oy, w, mm, (float*)d_out);
}